// round 6
// baseline (speedup 1.0000x reference)
#include <cuda_runtime.h>
#include <cuda_bf16.h>
#include <cstdint>

// out[n] = 0.1*Ax[n] - 0.1*deg[n]*x[n] + 0.9*(S[n] - cnt[n]*x[n]^2)
//
// Gathers of x served from CLUSTER-DISTRIBUTED SHARED MEMORY:
//   8-CTA cluster, each CTA holds a 65536-node slice of x quantized to u16
//   fixed point (x*65536). 8*65536 = 524288 >= N. Gather = mapa + ld.shared::cluster.
//   This removes all 26M gather ops from L2; only the 31M packed atomics remain.
//
// Per-node 64-bit packed accumulator (single RED.E.ADD.U64 per contribution):
//   bits [ 0:40)  fixed-point sum of (0.1*x[src]) and (0.9*p), scale 2^30
//   bits [40:52)  hyper slot count
//   bits [52:64)  adjacency degree

#define MAX_N     524288
#define SLICE     65536          // nodes per CTA slice (u16 each -> 128KB smem)
#define FX_SCALE  1073741824.0f  // 2^30
#define CLUSTER_X 8
#define TPB       1024

__device__ unsigned long long g_acc[MAX_N];

__device__ __forceinline__ unsigned long long pack_hyper(float v) {
    return (1ULL << 40) | (unsigned long long)__float2uint_rn(v * FX_SCALE);
}
__device__ __forceinline__ unsigned long long pack_adj(float v) {
    return (1ULL << 52) | (unsigned long long)__float2uint_rn(v * FX_SCALE);
}

__device__ __forceinline__ uint32_t smem_u32(const void* p) {
    uint32_t a;
    asm("{ .reg .u64 t; cvta.to.shared.u64 t, %1; cvt.u32.u64 %0, t; }"
        : "=r"(a) : "l"(p));
    return a;
}

// Gather quantized x[idx] from the cluster's distributed smem.
__device__ __forceinline__ float gather_x(uint32_t smem_base, int idx) {
    uint32_t rank = ((uint32_t)idx) >> 16;          // which CTA in cluster
    uint32_t local = smem_base + ((((uint32_t)idx) & 65535u) << 1);
    uint32_t remote;
    unsigned short v;
    asm volatile(
        "{\n\t"
        "mapa.shared::cluster.u32 %0, %2, %3;\n\t"
        "ld.shared::cluster.u16 %1, [%0];\n\t"
        "}"
        : "=r"(remote), "=h"(v) : "r"(local), "r"(rank));
    return (float)v * (1.0f / 65536.0f);
}

extern __shared__ unsigned short s_x[];   // SLICE u16 values

__global__ void __launch_bounds__(TPB, 1) __cluster_dims__(CLUSTER_X, 1, 1)
edge_kernel(const float* __restrict__ x, int N,
            const int*   __restrict__ he,  int nH,
            const int*   __restrict__ adj, int nA)
{
    const uint32_t sbase = smem_u32(s_x);

    // ---- stage this CTA's x slice into smem as u16 fixed point ----
    uint32_t crank;
    asm("mov.u32 %0, %%cluster_ctarank;" : "=r"(crank));
    {
        int base = (int)crank * SLICE;
        for (int i = threadIdx.x; i < SLICE; i += TPB) {
            int gi = base + i;
            unsigned short q = 0;
            if (gi < N) {
                uint32_t u = __float2uint_rn(x[gi] * 65536.0f);
                q = (unsigned short)min(u, 65535u);
            }
            s_x[i] = q;
        }
    }
    asm volatile("barrier.cluster.arrive.aligned;" ::: "memory");
    asm volatile("barrier.cluster.wait.aligned;" ::: "memory");

    const int tid    = blockIdx.x * TPB + threadIdx.x;
    const int stride = gridDim.x * TPB;

    // ---- hyper edges: groups of 4 edges (12 ints = 3x int4) ----
    {
        const int nGroups = nH >> 2;
        const int4* he4 = (const int4*)he;
        for (int g = tid; g < nGroups; g += stride) {
            int4 a = he4[3 * g + 0];
            int4 b = he4[3 * g + 1];
            int4 c = he4[3 * g + 2];
            int idx[12] = { a.x, a.y, a.z, a.w,
                            b.x, b.y, b.z, b.w,
                            c.x, c.y, c.z, c.w };
            float xv[8];
            #pragma unroll
            for (int e = 0; e < 4; e++) {
                xv[2 * e + 0] = gather_x(sbase, idx[3 * e + 1]);
                xv[2 * e + 1] = gather_x(sbase, idx[3 * e + 2]);
            }
            #pragma unroll
            for (int e = 0; e < 4; e++) {
                float p = 0.9f * xv[2 * e + 0] * xv[2 * e + 1];
                unsigned long long payload = pack_hyper(p);
                atomicAdd(&g_acc[idx[3 * e + 0]], payload);
                atomicAdd(&g_acc[idx[3 * e + 1]], payload);
                atomicAdd(&g_acc[idx[3 * e + 2]], payload);
            }
        }
        // scalar tail (nH % 4)
        int tailStart = nGroups << 2;
        int t = tailStart + tid;
        if (t < nH) {
            int i0 = he[3 * t + 0];
            int i1 = he[3 * t + 1];
            int i2 = he[3 * t + 2];
            float p = 0.9f * gather_x(sbase, i1) * gather_x(sbase, i2);
            unsigned long long payload = pack_hyper(p);
            atomicAdd(&g_acc[i0], payload);
            atomicAdd(&g_acc[i1], payload);
            atomicAdd(&g_acc[i2], payload);
        }
    }

    // ---- adjacency edges: groups of 2 edges (int4) ----
    {
        const int nGroups = nA >> 1;
        const int4* adj4 = (const int4*)adj;
        for (int g = tid; g < nGroups; g += stride) {
            int4 e = adj4[g];   // edge0=(e.x->e.y) edge1=(e.z->e.w)
            float s0 = gather_x(sbase, e.x);
            float s1 = gather_x(sbase, e.z);
            atomicAdd(&g_acc[e.y], pack_adj(0.1f * s0));
            atomicAdd(&g_acc[e.w], pack_adj(0.1f * s1));
        }
        int tailStart = nGroups << 1;
        int t = tailStart + tid;
        if (t < nA) {
            int s = adj[2 * t + 0];
            int d = adj[2 * t + 1];
            atomicAdd(&g_acc[d], pack_adj(0.1f * gather_x(sbase, s)));
        }
    }

    // keep smem alive until all cluster peers finished gathering
    asm volatile("barrier.cluster.arrive.aligned;" ::: "memory");
    asm volatile("barrier.cluster.wait.aligned;" ::: "memory");
}

__global__ void decode_kernel(const float* __restrict__ x,
                              float*       __restrict__ out,
                              int N)
{
    int n = blockIdx.x * blockDim.x + threadIdx.x;
    if (n >= N) return;
    unsigned long long a = g_acc[n];
    double sum = (double)(a & ((1ULL << 40) - 1)) * (1.0 / (double)FX_SCALE);
    int cntH = (int)((a >> 40) & 0xFFF);
    int degA = (int)((a >> 52) & 0xFFF);
    float xv = x[n];
    out[n] = (float)sum - 0.1f * (float)degA * xv - 0.9f * (float)cntH * xv * xv;
}

extern "C" void kernel_launch(void* const* d_in, const int* in_sizes, int n_in,
                              void* d_out, int out_size)
{
    const float* x   = (const float*)d_in[0];
    const int*   he  = (const int*)d_in[2];
    const int*   adj = (const int*)d_in[3];
    float*       out = (float*)d_out;

    const int nH = in_sizes[2] / 3;
    const int nA = in_sizes[3] / 2;
    const int N  = out_size;

    // zero the packed accumulator (memset node is graph-capturable)
    void* accPtr = nullptr;
    cudaGetSymbolAddress(&accPtr, g_acc);
    cudaMemsetAsync(accPtr, 0, (size_t)N * sizeof(unsigned long long), 0);

    // 128KB dynamic smem per CTA
    static int attrDone = 0;
    cudaFuncSetAttribute(edge_kernel,
                         cudaFuncAttributeMaxDynamicSharedMemorySize,
                         SLICE * (int)sizeof(unsigned short));
    (void)attrDone;

    // 144 CTAs = 18 portable clusters of 8; 1 CTA/SM (128KB smem each)
    const int grid = 144;
    edge_kernel<<<grid, TPB, SLICE * sizeof(unsigned short)>>>(
        x, N, he, nH, adj, nA);

    int decBlocks = (N + 255) / 256;
    decode_kernel<<<decBlocks, 256>>>(x, out, N);
}

// round 7
// speedup vs baseline: 2.9375x; 2.9375x over previous
#include <cuda_runtime.h>
#include <cuda_bf16.h>
#include <cstdint>

// out[n] = 0.1*Ax[n] - 0.1*deg[n]*x[n] + 0.9*(S[n] - cnt[n]*x[n]^2)
//
// Architecture (back to R5's scatter-to-L2, which measured fastest):
//   - x quantized once to u16 (1MB table) -> gathers have 2x L1 residency
//   - edge lists read with streaming hint (__ldcs) so they don't evict x
//   - one packed 64-bit RED.ADD per edge slot:
//       bits [ 0:40) fixed-point sum (0.1*x[src] / 0.9*p), scale 2^30
//       bits [40:52) hyper slot count
//       bits [52:64) adjacency degree
//   - decode pass uses exact fp32 x for deg*x and cnt*x^2 terms

#define MAX_N    524288
#define FX_SCALE 1073741824.0f   // 2^30
#define XQ_SCALE 65536.0f

__device__ unsigned long long g_acc[MAX_N];
__device__ unsigned short     g_xq[MAX_N];

__device__ __forceinline__ unsigned long long pack_hyper(float v) {
    return (1ULL << 40) | (unsigned long long)__float2uint_rn(v * FX_SCALE);
}
__device__ __forceinline__ unsigned long long pack_adj(float v) {
    return (1ULL << 52) | (unsigned long long)__float2uint_rn(v * FX_SCALE);
}

__device__ __forceinline__ float xq_val(int idx) {
    return (float)__ldg(&g_xq[idx]) * (1.0f / XQ_SCALE);
}

__global__ void quant_kernel(const float* __restrict__ x, int N)
{
    int n = blockIdx.x * blockDim.x + threadIdx.x;
    if (n < N) {
        uint32_t u = __float2uint_rn(__ldcs(x + n) * XQ_SCALE);
        g_xq[n] = (unsigned short)min(u, 65535u);
    }
}

__global__ void edge_kernel(const int* __restrict__ he,   // [nH*3]
                            int nH,
                            const int* __restrict__ adj,  // [nA*2]
                            int nA,
                            int hyperBlocks)
{
    if ((int)blockIdx.x < hyperBlocks) {
        // ---- hyper edges: 4 edges (12 ints) per thread via 3x streaming int4 ----
        const int g = blockIdx.x * blockDim.x + threadIdx.x;
        const int nGroups = nH >> 2;

        if (g < nGroups) {
            const int4* he4 = (const int4*)he;
            int4 a = __ldcs(he4 + 3 * g + 0);
            int4 b = __ldcs(he4 + 3 * g + 1);
            int4 c = __ldcs(he4 + 3 * g + 2);
            int idx[12] = { a.x, a.y, a.z, a.w,
                            b.x, b.y, b.z, b.w,
                            c.x, c.y, c.z, c.w };
            // issue all gathers first for MLP
            float xv[8];
            #pragma unroll
            for (int e = 0; e < 4; e++) {
                xv[2 * e + 0] = xq_val(idx[3 * e + 1]);
                xv[2 * e + 1] = xq_val(idx[3 * e + 2]);
            }
            #pragma unroll
            for (int e = 0; e < 4; e++) {
                float p = 0.9f * xv[2 * e + 0] * xv[2 * e + 1];
                unsigned long long payload = pack_hyper(p);
                atomicAdd(&g_acc[idx[3 * e + 0]], payload);
                atomicAdd(&g_acc[idx[3 * e + 1]], payload);
                atomicAdd(&g_acc[idx[3 * e + 2]], payload);
            }
        }
        // scalar tail (nH % 4)
        int tailStart = nGroups << 2;
        int t = tailStart + g;
        if (t < nH && g < (nH - tailStart)) {
            int i0 = he[3 * t + 0];
            int i1 = he[3 * t + 1];
            int i2 = he[3 * t + 2];
            float p = 0.9f * xq_val(i1) * xq_val(i2);
            unsigned long long payload = pack_hyper(p);
            atomicAdd(&g_acc[i0], payload);
            atomicAdd(&g_acc[i1], payload);
            atomicAdd(&g_acc[i2], payload);
        }
    } else {
        // ---- adjacency edges: 4 edges per thread via 2x streaming int4 ----
        const int g = ((int)blockIdx.x - hyperBlocks) * blockDim.x + threadIdx.x;
        const int nGroups = nA >> 2;

        if (g < nGroups) {
            const int4* adj4 = (const int4*)adj;
            int4 e0 = __ldcs(adj4 + 2 * g + 0);  // (s0,d0,s1,d1)
            int4 e1 = __ldcs(adj4 + 2 * g + 1);  // (s2,d2,s3,d3)
            float s0 = xq_val(e0.x);
            float s1 = xq_val(e0.z);
            float s2 = xq_val(e1.x);
            float s3 = xq_val(e1.z);
            atomicAdd(&g_acc[e0.y], pack_adj(0.1f * s0));
            atomicAdd(&g_acc[e0.w], pack_adj(0.1f * s1));
            atomicAdd(&g_acc[e1.y], pack_adj(0.1f * s2));
            atomicAdd(&g_acc[e1.w], pack_adj(0.1f * s3));
        }
        int tailStart = nGroups << 2;
        int t = tailStart + g;
        if (t < nA && g < (nA - tailStart)) {
            int s = adj[2 * t + 0];
            int d = adj[2 * t + 1];
            atomicAdd(&g_acc[d], pack_adj(0.1f * xq_val(s)));
        }
    }
}

__global__ void decode_kernel(const float* __restrict__ x,
                              float*       __restrict__ out,
                              int N)
{
    int n = blockIdx.x * blockDim.x + threadIdx.x;
    if (n >= N) return;
    unsigned long long a = g_acc[n];
    double sum = (double)(a & ((1ULL << 40) - 1)) * (1.0 / (double)FX_SCALE);
    int cntH = (int)((a >> 40) & 0xFFF);
    int degA = (int)((a >> 52) & 0xFFF);
    float xv = x[n];
    out[n] = (float)sum - 0.1f * (float)degA * xv - 0.9f * (float)cntH * xv * xv;
}

extern "C" void kernel_launch(void* const* d_in, const int* in_sizes, int n_in,
                              void* d_out, int out_size)
{
    const float* x   = (const float*)d_in[0];
    const int*   he  = (const int*)d_in[2];
    const int*   adj = (const int*)d_in[3];
    float*       out = (float*)d_out;

    const int nH = in_sizes[2] / 3;
    const int nA = in_sizes[3] / 2;
    const int N  = out_size;

    // zero packed accumulators (graph-capturable memset node)
    void* accPtr = nullptr;
    cudaGetSymbolAddress(&accPtr, g_acc);
    cudaMemsetAsync(accPtr, 0, (size_t)N * sizeof(unsigned long long), 0);

    // maximize L1 cache (no smem used by edge_kernel)
    cudaFuncSetAttribute(edge_kernel,
                         cudaFuncAttributePreferredSharedMemoryCarveout, 0);

    const int threads = 256;

    // build u16 x table (1MB, L1-friendly)
    quant_kernel<<<(N + threads - 1) / threads, threads>>>(x, N);

    int hyperBlocks = ((nH >> 2) + threads - 1) / threads;
    if (hyperBlocks < 1) hyperBlocks = 1;
    int adjBlocks = ((nA >> 2) + threads - 1) / threads;
    if (adjBlocks < 1) adjBlocks = 1;

    edge_kernel<<<hyperBlocks + adjBlocks, threads>>>(he, nH, adj, nA, hyperBlocks);

    int decBlocks = (N + threads - 1) / threads;
    decode_kernel<<<decBlocks, threads>>>(x, out, N);
}